// round 8
// baseline (speedup 1.0000x reference)
#include <cuda_runtime.h>

#define CCH 128
#define OCH 128
#define HH  56
#define WW  56
#define BB  32

#define NTHR 448      // 14 warps: og = tid&15 (8 o each, 4 f32x2 pairs), wg = tid>>4 (2 w each)

// scratch: intermediate activations + quantized (transposed) weights
__device__ float g_t[(size_t)BB * CCH * HH * WW];     // ~51.4 MB
__device__ float g_w1[9 * CCH * OCH];                  // [i][c][o]
__device__ float g_w2[9 * CCH * OCH];

// Effective LSQ alpha, matching jax grad_scale forward rounding exactly:
//   g computed in double (numpy), cast to f32 per use;
//   a_eff = fl(a*g32) + fl(a*fl32(1-g))
__device__ __forceinline__ float lsq_alpha_eff(float a, double g) {
    float s32 = (float)g;
    float om  = (float)(1.0 - g);
    return __fadd_rn(__fmul_rn(a, s32), __fmul_rn(a, om));
}

// packed fp32x2 helpers (sm_103a FFMA2 path)
__device__ __forceinline__ unsigned long long dup2(float x) {
    unsigned long long r;
    asm("mov.b64 %0, {%1, %1};" : "=l"(r) : "f"(x));
    return r;
}
__device__ __forceinline__ unsigned long long ffma2(unsigned long long a,
                                                    unsigned long long b,
                                                    unsigned long long c) {
    unsigned long long d;
    asm("fma.rn.f32x2 %0, %1, %2, %3;" : "=l"(d) : "l"(a), "l"(b), "l"(c));
    return d;
}
__device__ __forceinline__ void unpack2(unsigned long long v, float& lo, float& hi) {
    asm("mov.b64 {%0, %1}, %2;" : "=f"(lo), "=f"(hi) : "l"(v));
}

// wq_t[i][c][o] = round(clip(W[i][o][c]/a_eff, -4, 3)) * a_eff
__global__ void quant_w_kernel(const float* __restrict__ W,
                               const float* __restrict__ a_w,
                               float* __restrict__ wt) {
    int idx = blockIdx.x * blockDim.x + threadIdx.x;
    if (idx >= 9 * CCH * OCH) return;
    int o = idx % OCH;
    int c = (idx / OCH) % CCH;
    int i = idx / (OCH * CCH);
    const double gw = 1.0 / sqrt((double)(OCH * CCH * 3));   // 1/sqrt(49152)
    float a = lsq_alpha_eff(a_w[i], gw);
    float v = __fdiv_rn(W[((size_t)i * OCH + o) * CCH + c], a);
    v = fminf(fmaxf(v, -4.f), 3.f);
    wt[idx] = __fmul_rn(rintf(v), a);
}

// One block = one (b, h) output row: out[b][0..127][h][0..55]
__global__ __launch_bounds__(NTHR, 1)
void conv_kernel(const float* __restrict__ xin,       // [B][C][H][W]
                 const float* __restrict__ wqt,       // [9][C][O], i = dw*3+dh
                 const float* __restrict__ ap_ptr,    // scalar alpha_p
                 const float* __restrict__ gamma, const float* __restrict__ beta,
                 const float* __restrict__ mean,  const float* __restrict__ var,
                 const float* __restrict__ resid,
                 float* __restrict__ out,
                 int add_res) {
    extern __shared__ float smem[];
    float* xs = smem;                    // [128 c][58 w] one input row (w offset +1)
    float* ws = smem + CCH * 58;         // [3 dw][32 cc][128 o]

    const int h   = blockIdx.x;
    const int b   = blockIdx.y;
    const int tid = threadIdx.x;
    const int og  = tid & 15;
    const int wg  = tid >> 4;            // 0..27
    const int o0  = og * 8;
    const int w0  = wg * 2;

    // effective psum alpha (jax grad_scale forward)
    const double gp = 1.0 / sqrt((double)BB * OCH * HH * WW * 3.0);
    const float ap = lsq_alpha_eff(ap_ptr[0], gp);

    // out accumulator (scalar, exact multiples of ap)
    float out_sc[8][2];
    #pragma unroll
    for (int oi = 0; oi < 8; ++oi) { out_sc[oi][0] = 0.f; out_sc[oi][1] = 0.f; }

    for (int r = 0; r < 3; ++r) {           // input row h+r-1
        // stage one padded input row [128][58]
        {
            const int hs = h + r - 1;
            const bool hok = (unsigned)hs < HH;
            const float* xrow = xin + (((size_t)b * CCH) * HH + hs) * WW;
            for (int idx = tid; idx < CCH * 58; idx += NTHR) {
                int wi = idx % 58;
                int c  = idx / 58;
                int w  = wi - 1;
                float v = 0.f;
                if (hok && (unsigned)w < WW)
                    v = xrow[(size_t)c * (HH * WW) + w];
                xs[idx] = v;
            }
        }

        unsigned long long facc[3][4][2];   // [dw][o-pair][w]
        #pragma unroll
        for (int dw = 0; dw < 3; ++dw)
            #pragma unroll
            for (int op = 0; op < 4; ++op) {
                facc[dw][op][0] = 0ull; facc[dw][op][1] = 0ull;
            }

        for (int ch = 0; ch < 4; ++ch) {    // 32-channel chunks
            // stage weights [3 dw][32 cc][128 o] for this (r, chunk)
            for (int idx = tid; idx < 3 * 32 * OCH; idx += NTHR) {
                int o  = idx & (OCH - 1);
                int t2 = idx >> 7;          // dw*32 + cc
                int cc = t2 & 31;
                int dw = t2 >> 5;
                ws[idx] = wqt[((size_t)(dw * 3 + r) * CCH + (ch * 32 + cc)) * OCH + o];
            }
            __syncthreads();                // xs + ws ready

            const float* xbase = xs + (ch * 32) * 58 + w0;   // +cc*58 inside
            #pragma unroll 4
            for (int cc = 0; cc < 32; ++cc) {
                // x values at w = w0-1 .. w0+2  (8B-aligned pairs)
                float2 xa = *(const float2*)(xbase + cc * 58);
                float2 xb = *(const float2*)(xbase + cc * 58 + 2);
                unsigned long long xd[4];
                xd[0] = dup2(xa.x); xd[1] = dup2(xa.y);
                xd[2] = dup2(xb.x); xd[3] = dup2(xb.y);
                const float* wrow = ws + cc * OCH + o0;
                #pragma unroll
                for (int dw = 0; dw < 3; ++dw) {
                    ulonglong2 wp01 = *(const ulonglong2*)(wrow + dw * 32 * OCH);
                    ulonglong2 wp23 = *(const ulonglong2*)(wrow + dw * 32 * OCH + 4);
                    facc[dw][0][0] = ffma2(wp01.x, xd[dw],     facc[dw][0][0]);
                    facc[dw][0][1] = ffma2(wp01.x, xd[dw + 1], facc[dw][0][1]);
                    facc[dw][1][0] = ffma2(wp01.y, xd[dw],     facc[dw][1][0]);
                    facc[dw][1][1] = ffma2(wp01.y, xd[dw + 1], facc[dw][1][1]);
                    facc[dw][2][0] = ffma2(wp23.x, xd[dw],     facc[dw][2][0]);
                    facc[dw][2][1] = ffma2(wp23.x, xd[dw + 1], facc[dw][2][1]);
                    facc[dw][3][0] = ffma2(wp23.y, xd[dw],     facc[dw][3][0]);
                    facc[dw][3][1] = ffma2(wp23.y, xd[dw + 1], facc[dw][3][1]);
                }
            }
            __syncthreads();                // consumed; safe to restage ws/xs
        }

        // per-shift LSQ psum quantization, then accumulate (exact multiples of ap)
        #pragma unroll
        for (int dw = 0; dw < 3; ++dw)
            #pragma unroll
            for (int op = 0; op < 4; ++op)
                #pragma unroll
                for (int wi = 0; wi < 2; ++wi) {
                    float lo, hi;
                    unpack2(facc[dw][op][wi], lo, hi);
                    float ql = fminf(fmaxf(__fdiv_rn(lo, ap), -4.f), 3.f);
                    float qh = fminf(fmaxf(__fdiv_rn(hi, ap), -4.f), 3.f);
                    out_sc[2 * op][wi]     = __fadd_rn(out_sc[2 * op][wi],     __fmul_rn(rintf(ql), ap));
                    out_sc[2 * op + 1][wi] = __fadd_rn(out_sc[2 * op + 1][wi], __fmul_rn(rintf(qh), ap));
                }
    }

    // epilogue: BN (+residual) + ReLU with jax-matching rounding (NO fma contraction)
    const size_t obase0 = ((size_t)b * OCH) * (HH * WW) + (size_t)h * WW + w0;
    #pragma unroll
    for (int oi = 0; oi < 8; ++oi) {
        int o = o0 + oi;
        float invs = __fdiv_rn(gamma[o], sqrtf(__fadd_rn(var[o], 1e-5f)));
        float sh   = __fadd_rn(beta[o], -__fmul_rn(mean[o], invs));
        size_t base = obase0 + (size_t)o * (HH * WW);
        float v0 = __fadd_rn(__fmul_rn(out_sc[oi][0], invs), sh);
        float v1 = __fadd_rn(__fmul_rn(out_sc[oi][1], invs), sh);
        if (add_res) {
            float2 rr = *(const float2*)(resid + base);
            v0 = __fadd_rn(v0, rr.x);
            v1 = __fadd_rn(v1, rr.y);
        }
        float2 s;
        s.x = fmaxf(v0, 0.f);
        s.y = fmaxf(v1, 0.f);
        *(float2*)(out + base) = s;
    }
}

extern "C" void kernel_launch(void* const* d_in, const int* in_sizes, int n_in,
                              void* d_out, int out_size) {
    const float* x    = (const float*)d_in[0];
    const float* W1   = (const float*)d_in[1];
    const float* a_w1 = (const float*)d_in[2];
    const float* W2   = (const float*)d_in[3];
    const float* a_w2 = (const float*)d_in[4];
    const float* a_p1 = (const float*)d_in[5];
    const float* a_p2 = (const float*)d_in[6];
    const float* g1   = (const float*)d_in[7];
    const float* b1   = (const float*)d_in[8];
    const float* m1   = (const float*)d_in[9];
    const float* v1   = (const float*)d_in[10];
    const float* g2   = (const float*)d_in[11];
    const float* b2   = (const float*)d_in[12];
    const float* m2   = (const float*)d_in[13];
    const float* v2   = (const float*)d_in[14];
    float* out = (float*)d_out;

    float *t, *w1q, *w2q;
    cudaGetSymbolAddress((void**)&t,   g_t);
    cudaGetSymbolAddress((void**)&w1q, g_w1);
    cudaGetSymbolAddress((void**)&w2q, g_w2);

    const int smem_bytes = (CCH * 58 + 3 * 32 * OCH) * (int)sizeof(float); // 78848
    cudaFuncSetAttribute(conv_kernel, cudaFuncAttributeMaxDynamicSharedMemorySize, smem_bytes);

    const int nw = 9 * CCH * OCH;
    quant_w_kernel<<<(nw + 255) / 256, 256>>>(W1, a_w1, w1q);
    quant_w_kernel<<<(nw + 255) / 256, 256>>>(W2, a_w2, w2q);

    dim3 grid(HH, BB);
    conv_kernel<<<grid, NTHR, smem_bytes>>>(x, w1q, a_p1, g1, b1, m1, v1, nullptr, t, 0);
    conv_kernel<<<grid, NTHR, smem_bytes>>>(t, w2q, a_p2, g2, b2, m2, v2, x, out, 1);
}